// round 6
// baseline (speedup 1.0000x reference)
#include <cuda_runtime.h>
#include <cuda_fp16.h>
#include <cstdint>

#define Sq   2048
#define DKd  64
#define TQt  128
#define NTHR 512
#define NBH  64
#define NKT  (Sq / TQt)   // 16

#define SB   144    // Q/K/V row stride in bytes (72 fp16)
#define SPB  272    // P row stride in bytes (136 fp16)

// smem byte offsets
#define OFF_QHI  0
#define OFF_QLO  18432
#define OFF_KHI  36864
#define OFF_KLO  55296
#define OFF_VHI  73728
#define OFF_VLO  92160
#define OFF_P    110592
#define OFF_REDF 145408
#define OFF_REDC 147456
#define OFF_INV  149504
#define SMEM_BYTES 150016

#define MMAH(c, a, b) \
    asm volatile("mma.sync.aligned.m16n8k16.row.col.f32.f16.f16.f32 " \
        "{%0,%1,%2,%3}, {%4,%5,%6,%7}, {%8,%9}, {%0,%1,%2,%3};" \
        : "+f"((c)[0]), "+f"((c)[1]), "+f"((c)[2]), "+f"((c)[3]) \
        : "r"((a)[0]), "r"((a)[1]), "r"((a)[2]), "r"((a)[3]), \
          "r"((b)[0]), "r"((b)[1]))

__device__ __forceinline__ uint32_t smem_u32(const void* p) {
    uint32_t a;
    asm("{ .reg .u64 t; cvta.to.shared.u64 t, %1; cvt.u32.u64 %0, t; }" : "=r"(a) : "l"(p));
    return a;
}
__device__ __forceinline__ void ldm4(uint32_t r[4], uint32_t addr) {
    asm volatile("ldmatrix.sync.aligned.m8n8.x4.shared.b16 {%0,%1,%2,%3}, [%4];"
                 : "=r"(r[0]), "=r"(r[1]), "=r"(r[2]), "=r"(r[3]) : "r"(addr));
}
__device__ __forceinline__ void ldm2t(uint32_t& r0, uint32_t& r1, uint32_t addr) {
    asm volatile("ldmatrix.sync.aligned.m8n8.x2.trans.shared.b16 {%0,%1}, [%2];"
                 : "=r"(r0), "=r"(r1) : "r"(addr));
}
// (a,b) -> fp16x2 hi, fp16x2 residual lo
__device__ __forceinline__ void split2h(float a, float b, uint32_t& hi, uint32_t& lo) {
    __half2 h = __floats2half2_rn(a, b);
    hi = *(uint32_t*)&h;
    float2 hf = __half22float2(h);
    __half2 l = __floats2half2_rn(a - hf.x, b - hf.y);
    lo = *(uint32_t*)&l;
}
__device__ __forceinline__ uint32_t packh(float a, float b) {
    __half2 h = __floats2half2_rn(a, b);
    return *(uint32_t*)&h;
}

// thread t owns row t>>2, cols (t&3)*16 .. +15 of a 128x64 fp32 tile
__device__ __forceinline__ void ldg_tile(const float* __restrict__ g, int t, float4 f[4]) {
    const float4* p = (const float4*)(g + (size_t)(t >> 2) * DKd + (t & 3) * 16);
    f[0] = p[0]; f[1] = p[1]; f[2] = p[2]; f[3] = p[3];
}
__device__ __forceinline__ void sts_split(char* smc, int off_hi, int off_lo, int t,
                                          const float4 f[4], bool lo_too) {
    uint32_t h[8], l[8];
    #pragma unroll
    for (int j = 0; j < 4; j++) {
        split2h(f[j].x, f[j].y, h[2 * j], l[2 * j]);
        split2h(f[j].z, f[j].w, h[2 * j + 1], l[2 * j + 1]);
    }
    int b = (t >> 2) * SB + (t & 3) * 32;
    *(uint4*)(smc + off_hi + b)      = make_uint4(h[0], h[1], h[2], h[3]);
    *(uint4*)(smc + off_hi + b + 16) = make_uint4(h[4], h[5], h[6], h[7]);
    if (lo_too) {
        *(uint4*)(smc + off_lo + b)      = make_uint4(l[0], l[1], l[2], l[3]);
        *(uint4*)(smc + off_lo + b + 16) = make_uint4(l[4], l[5], l[6], l[7]);
    }
}

__global__ __launch_bounds__(NTHR, 1)
void sdpa_mma_kernel(const float* __restrict__ Q,
                     const float* __restrict__ K,
                     const float* __restrict__ V,
                     float* __restrict__ out_ctx,
                     float* __restrict__ out_attn)
{
    extern __shared__ char smc[];
    const uint32_t smb = smem_u32(smc);
    const int t    = threadIdx.x;
    const int wid  = t >> 5;
    const int lane = t & 31;
    const int g    = lane >> 2;
    const int tg   = lane & 3;
    const int mw   = wid >> 2;
    const int nw   = wid & 3;
    const int bh   = blockIdx.y;
    const int qt   = blockIdx.x;
    const int q0   = qt * TQt;

    // per-lane ldmatrix address offsets
    const int aRow = (lane & 7) + ((lane >> 3) & 1) * 8;   // A (x4)
    const int aCol = (lane >> 4) * 8;
    const int bRow = (lane & 7) + (lane >> 4) * 8;          // B (x4)
    const int bCol = ((lane >> 3) & 1) * 8;
    const int vRow = lane & 15;                              // V (x2 trans)

    const float* Qb = Q + (size_t)bh * Sq * DKd;
    const float* Kb = K + (size_t)bh * Sq * DKd;
    const float* Vb = V + (size_t)bh * Sq * DKd;
    float* attn_q = out_attn + ((size_t)bh * Sq + q0) * Sq;

    // ---- zero-fill attn above the diagonal tiles (off critical path) ----
    {
        int zc0 = (qt + 1) * TQt;
        int zf4 = (Sq - zc0) >> 2;
        if (zf4 > 0) {
            float4 z = make_float4(0.f, 0.f, 0.f, 0.f);
            for (int idx = t; idx < TQt * zf4; idx += NTHR) {
                int rr = idx / zf4, c4 = idx - rr * zf4;
                *(float4*)(attn_q + (size_t)rr * Sq + zc0 + c4 * 4) = z;
            }
        }
    }

    // ---- prologue: Q tile + first K/V tiles in flight ----
    float4 pq[4], pk[4], pv[4];
    ldg_tile(Qb + (size_t)q0 * DKd, t, pq);
    ldg_tile(Kb, t, pk);
    ldg_tile(Vb, t, pv);
    sts_split(smc, OFF_QHI, OFF_QLO, t, pq, true);

    float sf[2][2] = {{0.f, 0.f}, {0.f, 0.f}};
    float sc[2][2] = {{0.f, 0.f}, {0.f, 0.f}};
    float av[2][2][4];
    #pragma unroll
    for (int mi = 0; mi < 2; mi++)
        #pragma unroll
        for (int ni = 0; ni < 2; ni++)
            #pragma unroll
            for (int e = 0; e < 4; e++) av[mi][ni][e] = 0.f;

    // ==================== SINGLE PASS over key tiles ====================
    for (int kt = 0; kt < NKT; kt++) {
        const bool causal = (kt <= qt);
        const bool diag   = (kt == qt);

        sts_split(smc, OFF_KHI, OFF_KLO, t, pk, causal);
        if (causal) sts_split(smc, OFF_VHI, OFF_VLO, t, pv, true);
        if (kt < NKT - 1) {
            ldg_tile(Kb + (size_t)(kt + 1) * TQt * DKd, t, pk);
            if (kt + 1 <= qt) ldg_tile(Vb + (size_t)(kt + 1) * TQt * DKd, t, pv);
        }
        __syncthreads();

        float c[2][4][4];
        #pragma unroll
        for (int mi = 0; mi < 2; mi++)
            #pragma unroll
            for (int ni = 0; ni < 4; ni++)
                #pragma unroll
                for (int e = 0; e < 4; e++) c[mi][ni][e] = 0.f;

        #pragma unroll
        for (int ks = 0; ks < 4; ks++) {
            int kc = ks * 16;
            uint32_t qh[2][4], ql[2][4], bhf[2][4], blf[2][4];
            #pragma unroll
            for (int mi = 0; mi < 2; mi++) {
                int r0 = mw * 32 + mi * 16 + aRow;
                ldm4(qh[mi], smb + OFF_QHI + r0 * SB + (kc + aCol) * 2);
                if (causal)
                    ldm4(ql[mi], smb + OFF_QLO + r0 * SB + (kc + aCol) * 2);
            }
            #pragma unroll
            for (int p = 0; p < 2; p++) {
                int n0 = nw * 32 + p * 16 + bRow;
                ldm4(bhf[p], smb + OFF_KHI + n0 * SB + (kc + bCol) * 2);
                if (causal)
                    ldm4(blf[p], smb + OFF_KLO + n0 * SB + (kc + bCol) * 2);
            }
            #pragma unroll
            for (int mi = 0; mi < 2; mi++)
                #pragma unroll
                for (int ni = 0; ni < 4; ni++) {
                    const uint32_t* bb = &bhf[ni >> 1][(ni & 1) * 2];
                    MMAH(c[mi][ni], qh[mi], bb);
                    if (causal) {
                        const uint32_t* bl = &blf[ni >> 1][(ni & 1) * 2];
                        MMAH(c[mi][ni], qh[mi], bl);
                        MMAH(c[mi][ni], ql[mi], bb);
                    }
                }
        }

        // e = exp(s); accumulate sums; causal: store e (unnormalized) to attn + P smem
        #pragma unroll
        for (int mi = 0; mi < 2; mi++) {
            int rloc0 = mw * 32 + mi * 16 + g;
            int rg = q0 + rloc0;
            #pragma unroll
            for (int ni = 0; ni < 4; ni++) {
                int cl = nw * 32 + ni * 8 + 2 * tg;
                int cg = kt * TQt + cl;
                float e0 = __expf(c[mi][ni][0] * 0.125f);
                float e1 = __expf(c[mi][ni][1] * 0.125f);
                float e2 = __expf(c[mi][ni][2] * 0.125f);
                float e3 = __expf(c[mi][ni][3] * 0.125f);
                sf[mi][0] += e0 + e1;
                sf[mi][1] += e2 + e3;
                if (causal) {
                    if (diag) {
                        e0 = (cg     <= rg) ? e0 : 0.f;
                        e1 = (cg + 1 <= rg) ? e1 : 0.f;
                        e2 = (cg     <= rg + 8) ? e2 : 0.f;
                        e3 = (cg + 1 <= rg + 8) ? e3 : 0.f;
                    }
                    sc[mi][0] += e0 + e1;
                    sc[mi][1] += e2 + e3;
                    *(float2*)(attn_q + (size_t)rloc0 * Sq + cg)       = make_float2(e0, e1);
                    *(float2*)(attn_q + (size_t)(rloc0 + 8) * Sq + cg) = make_float2(e2, e3);
                    *(uint32_t*)(smc + OFF_P + rloc0 * SPB + cl * 2)       = packh(e0, e1);
                    *(uint32_t*)(smc + OFF_P + (rloc0 + 8) * SPB + cl * 2) = packh(e2, e3);
                }
            }
        }

        if (causal) {
            __syncthreads();
            // ctx_unnorm += e @ V (2-term: e*Vhi + e*Vlo)
            #pragma unroll
            for (int ks = 0; ks < 8; ks++) {
                int kc = ks * 16;
                uint32_t ap[2][4];
                #pragma unroll
                for (int mi = 0; mi < 2; mi++) {
                    int r0 = mw * 32 + mi * 16 + aRow;
                    ldm4(ap[mi], smb + OFF_P + r0 * SPB + (kc + aCol) * 2);
                }
                #pragma unroll
                for (int ni = 0; ni < 2; ni++) {
                    int dv0 = nw * 16 + ni * 8;
                    uint32_t bhv[2], blv[2];
                    ldm2t(bhv[0], bhv[1], smb + OFF_VHI + (kc + vRow) * SB + dv0 * 2);
                    ldm2t(blv[0], blv[1], smb + OFF_VLO + (kc + vRow) * SB + dv0 * 2);
                    #pragma unroll
                    for (int mi = 0; mi < 2; mi++) {
                        MMAH(av[mi][ni], ap[mi], bhv);
                        MMAH(av[mi][ni], ap[mi], blv);
                    }
                }
            }
        }
        __syncthreads();
    }

    // ---- reduce denominators: lanes (tg) then warps (nw) ----
    {
        float* redf = (float*)(smc + OFF_REDF);
        float* redc = (float*)(smc + OFF_REDC);
        #pragma unroll
        for (int mi = 0; mi < 2; mi++)
            #pragma unroll
            for (int rr = 0; rr < 2; rr++) {
                float vf = sf[mi][rr], vc = sc[mi][rr];
                vf += __shfl_xor_sync(0xffffffffu, vf, 1);
                vf += __shfl_xor_sync(0xffffffffu, vf, 2);
                vc += __shfl_xor_sync(0xffffffffu, vc, 1);
                vc += __shfl_xor_sync(0xffffffffu, vc, 2);
                if (tg == 0) {
                    int row = mw * 32 + mi * 16 + rr * 8 + g;
                    redf[row * 4 + nw] = vf;
                    redc[row * 4 + nw] = vc;
                }
            }
    }
    __syncthreads();
    if (t < 128) {
        const float* rf = (const float*)(smc + OFF_REDF) + t * 4;
        const float* rc = (const float*)(smc + OFF_REDC) + t * 4;
        float vf = (rf[0] + rf[1]) + (rf[2] + rf[3]);
        float vc = (rc[0] + rc[1]) + (rc[2] + rc[3]);
        ((float*)(smc + OFF_INV))[t] = 1.0f / (vc + 1e-8f * vf);
    }
    __syncthreads();

    float invr[2][2];
    #pragma unroll
    for (int mi = 0; mi < 2; mi++) {
        invr[mi][0] = ((const float*)(smc + OFF_INV))[mw * 32 + mi * 16 + g];
        invr[mi][1] = ((const float*)(smc + OFF_INV))[mw * 32 + mi * 16 + g + 8];
    }

    // ---- context output: scale unnormalized accumulators by inv ----
    #pragma unroll
    for (int mi = 0; mi < 2; mi++) {
        int rloc0 = mw * 32 + mi * 16 + g;
        #pragma unroll
        for (int ni = 0; ni < 2; ni++) {
            int cl = nw * 16 + ni * 8 + 2 * tg;
            *(float2*)(out_ctx + ((size_t)bh * Sq + q0 + rloc0) * DKd + cl) =
                make_float2(av[mi][ni][0] * invr[mi][0], av[mi][ni][1] * invr[mi][0]);
            *(float2*)(out_ctx + ((size_t)bh * Sq + q0 + rloc0 + 8) * DKd + cl) =
                make_float2(av[mi][ni][2] * invr[mi][1], av[mi][ni][3] * invr[mi][1]);
        }
    }

    // ---- rescale this CTA's causal attn region in place (mostly L2 hits) ----
    {
        const float* invf = (const float*)(smc + OFF_INV);
        int nc4 = ((qt + 1) * TQt) >> 2;   // float4s per row
        for (int idx = t; idx < TQt * nc4; idx += NTHR) {
            int row = idx / nc4;
            int c4  = idx - row * nc4;
            float s = invf[row];
            float4* p = (float4*)(attn_q + (size_t)row * Sq) + c4;
            float4 a = *p;
            a.x *= s; a.y *= s; a.z *= s; a.w *= s;
            *p = a;
        }
    }
}

extern "C" void kernel_launch(void* const* d_in, const int* in_sizes, int n_in,
                              void* d_out, int out_size)
{
    const float* Q = (const float*)d_in[0];
    const float* K = (const float*)d_in[1];
    const float* V = (const float*)d_in[2];
    float* ctx  = (float*)d_out;
    float* attn = (float*)d_out + (size_t)NBH * Sq * DKd;

    cudaFuncSetAttribute(sdpa_mma_kernel, cudaFuncAttributeMaxDynamicSharedMemorySize, SMEM_BYTES);
    dim3 grid(Sq / TQt, NBH);
    sdpa_mma_kernel<<<grid, NTHR, SMEM_BYTES>>>(Q, K, V, ctx, attn);
    (void)in_sizes; (void)n_in; (void)out_size;
}